// round 2
// baseline (speedup 1.0000x reference)
#include <cuda_runtime.h>
#include <cuda_bf16.h>
#include <cstdint>

// Problem constants (fixed by reference: B=256, C=512, H=W=14, D=32, A=2000)
#define BB   256
#define CC   512
#define HW   196
#define HW4  49          // 196/4 float4 per row
#define ND   32
#define NA   2000

// Scratch (no allocations allowed in kernel_launch)
__device__ float g_att[BB * CC];       // attended [B][C]

// ---------------------------------------------------------------------------
// Kernel 1: attended[b][c] = (1/196) * sum_hw mask[b][hw] * feat[b][c][hw]
// One warp per (b,c) row. Rows are 784 B = 49 float4 (16B-aligned).
// ---------------------------------------------------------------------------
__global__ void attend_kernel(const float4* __restrict__ feat,
                              const float4* __restrict__ mask) {
    int w    = (blockIdx.x * blockDim.x + threadIdx.x) >> 5;   // global warp = b*512+c
    int lane = threadIdx.x & 31;
    int b    = w >> 9;

    const float4* f = feat + (size_t)w * HW4;
    const float4* m = mask + (size_t)b * HW4;

    float4 v0 = f[lane];
    float4 m0 = m[lane];
    float s = v0.x * m0.x + v0.y * m0.y + v0.z * m0.z + v0.w * m0.w;
    if (lane < HW4 - 32) {                 // lanes 0..16 take the tail 17 float4
        float4 v1 = f[lane + 32];
        float4 m1 = m[lane + 32];
        s += v1.x * m1.x + v1.y * m1.y + v1.z * m1.z + v1.w * m1.w;
    }
    #pragma unroll
    for (int off = 16; off > 0; off >>= 1)
        s += __shfl_xor_sync(0xffffffffu, s, off);
    if (lane == 0)
        g_att[w] = s * (1.0f / (float)HW);
}

// ---------------------------------------------------------------------------
// Kernel 2: per-expert batched matvec with in-block bucketing.
//   grid = (A_TILES=4, experts=32, ZSLICES=4), block = 128 threads.
//   Each block: warp-ballot compaction builds the expert's sample list from
//   `instance` (L2-hot), then processes chunks of 8 samples: attended rows
//   staged in smem (16 KB); each thread accumulates 8 samples x 4 answers;
//   weight read once per chunk as float4 (coalesced 2 KB/block per c).
//   Deterministic: per-sample c-loop order is fixed regardless of bucketing.
// ---------------------------------------------------------------------------
#define S2_THREADS 128
#define S2_APT     4                       // answers per thread (float4)
#define A_TILE     (S2_THREADS * S2_APT)   // 512
#define A_TILES    4                       // 4*512 = 2048 >= 2000
#define CHUNK      8
#define ZSLICES    4

__global__ __launch_bounds__(S2_THREADS)
void expert_mv_kernel(const float* __restrict__ weight,
                      const float* __restrict__ bias,
                      const int*   __restrict__ instance,
                      float* __restrict__ out) {
    const int d = blockIdx.y;
    const int z = blockIdx.z;

    __shared__ int   sinst[BB];
    __shared__ int   slist[BB];
    __shared__ int   scnt;
    __shared__ float satt[CHUNK * CC];     // 8 x 512 floats = 16 KB

    // ---- in-block bucketing: build this expert's sample list ----
    for (int t = threadIdx.x; t < BB; t += S2_THREADS)
        sinst[t] = instance[t];
    __syncthreads();
    if (threadIdx.x < 32) {
        int lane = threadIdx.x;
        int base = 0;
        #pragma unroll
        for (int g = 0; g < BB / 32; g++) {
            int b = g * 32 + lane;
            bool m = (sinst[b] == d);
            unsigned bal = __ballot_sync(0xffffffffu, m);
            if (m) slist[base + __popc(bal & ((1u << lane) - 1u))] = b;
            base += __popc(bal);
        }
        if (lane == 0) scnt = base;
    }
    __syncthreads();

    const int cnt = scnt;
    const int nchunks = (cnt + CHUNK - 1) / CHUNK;

    const int a0 = blockIdx.x * A_TILE + threadIdx.x * S2_APT;
    const bool a_ok = (a0 < NA);           // a0 % 4 == 0, NA % 4 == 0
    const float* wp = weight + (size_t)d * CC * NA + a0;

    for (int ch = z; ch < nchunks; ch += ZSLICES) {
        const int s0 = ch * CHUNK;
        const int ns = min(CHUNK, cnt - s0);

        int bidx[CHUNK];
        #pragma unroll
        for (int i = 0; i < CHUNK; i++)
            bidx[i] = slist[min(s0 + i, cnt - 1)];

        // stage attended rows for this chunk into smem (coalesced, L2-hot)
        __syncthreads();   // protect smem from previous iteration's readers
        for (int t = threadIdx.x; t < CHUNK * CC; t += S2_THREADS) {
            int s = t >> 9;        // /512
            int c = t & (CC - 1);
            satt[t] = g_att[bidx[s] * CC + c];
        }
        __syncthreads();

        if (a_ok) {
            float4 acc[CHUNK];
            #pragma unroll
            for (int i = 0; i < CHUNK; i++)
                acc[i] = make_float4(0.f, 0.f, 0.f, 0.f);

            #pragma unroll 4
            for (int c = 0; c < CC; c++) {
                float4 wv = *reinterpret_cast<const float4*>(wp + (size_t)c * NA);
                #pragma unroll
                for (int i = 0; i < CHUNK; i++) {
                    float m = satt[i * CC + c];    // smem broadcast
                    acc[i].x += m * wv.x;
                    acc[i].y += m * wv.y;
                    acc[i].z += m * wv.z;
                    acc[i].w += m * wv.w;
                }
            }
            float4 bv = *reinterpret_cast<const float4*>(bias + (size_t)d * NA + a0);
            #pragma unroll
            for (int i = 0; i < CHUNK; i++) {
                if (i < ns) {
                    float4 r;
                    r.x = acc[i].x + bv.x;
                    r.y = acc[i].y + bv.y;
                    r.z = acc[i].z + bv.z;
                    r.w = acc[i].w + bv.w;
                    *reinterpret_cast<float4*>(out + (size_t)bidx[i] * NA + a0) = r;
                }
            }
        }
    }
}

// ---------------------------------------------------------------------------
// Launch: metadata order = mask, features, weight, bias, instance; out = f32.
// ---------------------------------------------------------------------------
extern "C" void kernel_launch(void* const* d_in, const int* in_sizes, int n_in,
                              void* d_out, int out_size) {
    const float* mask     = (const float*)d_in[0];   // [256,1,14,14]
    const float* features = (const float*)d_in[1];   // [256,512,14,14]
    const float* weight   = (const float*)d_in[2];   // [32,512,2000]
    const float* bias     = (const float*)d_in[3];   // [32,2000]
    const int*   instance = (const int*)d_in[4];     // [256]
    float*       out      = (float*)d_out;           // [256,2000]

    // one warp per (b,c): 256*512 warps, 8 warps/block
    attend_kernel<<<(BB * CC) / 8, 256>>>(
        reinterpret_cast<const float4*>(features),
        reinterpret_cast<const float4*>(mask));

    dim3 grid(A_TILES, ND, ZSLICES);
    expert_mv_kernel<<<grid, S2_THREADS>>>(weight, bias, instance, out);
}

// round 5
// speedup vs baseline: 1.7087x; 1.7087x over previous
#include <cuda_runtime.h>
#include <cuda_bf16.h>
#include <cstdint>

// Problem constants (fixed by reference: B=256, C=512, H=W=14, D=32, A=2000)
#define BB   256
#define CC   512
#define HW   196
#define HW4  49          // 196/4 float4 per row
#define ND   32
#define NA   2000

#define CSLICES 4
#define CSL     (CC / CSLICES)             // 128 channels per slice

// Scratch (no allocations allowed in kernel_launch)
__device__ float g_att[BB * CC];                    // attended [B][C]  (512 KB)
__device__ float g_part[CSLICES * BB * NA];         // partials [Z][B][A] (8 MB)

// ---------------------------------------------------------------------------
// Kernel 1: attended[b][c] = (1/196) * sum_hw mask[b][hw] * feat[b][c][hw]
// One warp per (b,c) row. Rows are 784 B = 49 float4 (16B-aligned).
// ---------------------------------------------------------------------------
__global__ void attend_kernel(const float4* __restrict__ feat,
                              const float4* __restrict__ mask) {
    int w    = (blockIdx.x * blockDim.x + threadIdx.x) >> 5;   // global warp = b*512+c
    int lane = threadIdx.x & 31;
    int b    = w >> 9;

    const float4* f = feat + (size_t)w * HW4;
    const float4* m = mask + (size_t)b * HW4;

    float4 v0 = f[lane];
    float4 m0 = m[lane];
    float s = v0.x * m0.x + v0.y * m0.y + v0.z * m0.z + v0.w * m0.w;
    if (lane < HW4 - 32) {                 // lanes 0..16 take the tail 17 float4
        float4 v1 = f[lane + 32];
        float4 m1 = m[lane + 32];
        s += v1.x * m1.x + v1.y * m1.y + v1.z * m1.z + v1.w * m1.w;
    }
    #pragma unroll
    for (int off = 16; off > 0; off >>= 1)
        s += __shfl_xor_sync(0xffffffffu, s, off);
    if (lane == 0)
        g_att[w] = s * (1.0f / (float)HW);
}

// ---------------------------------------------------------------------------
// Kernel 2: per-expert PARTIAL matvec, parallel over the C dimension.
//   grid = (A_TILES=4, experts=32, CSLICES=4), block = 128 threads.
//   Block (x=a-tile, y=expert d, z=c-slice) computes, for every sample b of
//   expert d:   part[z][b][a] = sum_{c in slice z} att[b][c] * W[d][c][a]
//   Weight is read ~once total (CHUNK=12 covers nearly all expert counts in
//   one pass). Deterministic: fixed c order, no atomics.
// ---------------------------------------------------------------------------
#define S2_THREADS 128
#define S2_APT     4                       // answers per thread (float4)
#define A_TILE     (S2_THREADS * S2_APT)   // 512
#define A_TILES    4                       // 4*512 = 2048 >= 2000
#define CHUNK      12

__global__ __launch_bounds__(S2_THREADS)
void expert_partial_kernel(const float* __restrict__ weight,
                           const int*   __restrict__ instance) {
    const int d  = blockIdx.y;
    const int z  = blockIdx.z;
    const int c0 = z * CSL;

    __shared__ int   sinst[BB];
    __shared__ int   slist[BB];
    __shared__ int   scnt;
    __shared__ float satt[CHUNK * CSL];    // 12 x 128 floats = 6 KB

    // ---- in-block bucketing: build this expert's sample list ----
    for (int t = threadIdx.x; t < BB; t += S2_THREADS)
        sinst[t] = instance[t];
    __syncthreads();
    if (threadIdx.x < 32) {
        int lane = threadIdx.x;
        int base = 0;
        #pragma unroll
        for (int g = 0; g < BB / 32; g++) {
            int b = g * 32 + lane;
            bool m = (sinst[b] == d);
            unsigned bal = __ballot_sync(0xffffffffu, m);
            if (m) slist[base + __popc(bal & ((1u << lane) - 1u))] = b;
            base += __popc(bal);
        }
        if (lane == 0) scnt = base;
    }
    __syncthreads();

    const int cnt = scnt;
    const int nchunks = (cnt + CHUNK - 1) / CHUNK;

    const int a0 = blockIdx.x * A_TILE + threadIdx.x * S2_APT;
    const bool a_ok = (a0 < NA);           // a0 % 4 == 0, NA % 4 == 0
    const float* wp = weight + ((size_t)d * CC + c0) * NA + a0;

    for (int ch = 0; ch < nchunks; ch++) {
        const int s0 = ch * CHUNK;
        const int ns = min(CHUNK, cnt - s0);

        int bidx[CHUNK];
        #pragma unroll
        for (int i = 0; i < CHUNK; i++)
            bidx[i] = slist[min(s0 + i, cnt - 1)];

        // stage attended slice rows for this chunk into smem
        __syncthreads();   // protect smem from previous iteration's readers
        for (int t = threadIdx.x; t < CHUNK * CSL; t += S2_THREADS) {
            int s = t / CSL;
            int c = t - s * CSL;
            satt[t] = g_att[bidx[s] * CC + c0 + c];
        }
        __syncthreads();

        if (a_ok) {
            float4 acc[CHUNK];
            #pragma unroll
            for (int i = 0; i < CHUNK; i++)
                acc[i] = make_float4(0.f, 0.f, 0.f, 0.f);

            // deep unroll: 8 independent LDG.128 in flight per thread
            #pragma unroll 8
            for (int c = 0; c < CSL; c++) {
                float4 wv = *reinterpret_cast<const float4*>(wp + (size_t)c * NA);
                #pragma unroll
                for (int i = 0; i < CHUNK; i++) {
                    float m = satt[i * CSL + c];   // smem broadcast
                    acc[i].x += m * wv.x;
                    acc[i].y += m * wv.y;
                    acc[i].z += m * wv.z;
                    acc[i].w += m * wv.w;
                }
            }
            #pragma unroll
            for (int i = 0; i < CHUNK; i++) {
                if (i < ns) {
                    float* o = g_part + ((size_t)z * BB + bidx[i]) * NA + a0;
                    *reinterpret_cast<float4*>(o) = acc[i];
                }
            }
        }
    }
}

// ---------------------------------------------------------------------------
// Kernel 3: out[b][a] = sum_z part[z][b][a] + bias[instance[b]][a]
// Two blocks per sample b (halves of the A range); fixed z-summation order.
// ---------------------------------------------------------------------------
#define RED_THREADS 256
#define RED_SPLIT   2

__global__ __launch_bounds__(RED_THREADS)
void reduce_kernel(const float* __restrict__ bias,
                   const int*   __restrict__ instance,
                   float* __restrict__ out) {
    const int b    = blockIdx.x;
    const int half = blockIdx.y;
    const int d = instance[b];
    const int NA4 = NA / 4;                        // 500 float4 per row
    const int t0 = half * (NA4 / RED_SPLIT);
    const int t1 = (half + 1 == RED_SPLIT) ? NA4 : t0 + NA4 / RED_SPLIT;

    for (int t = t0 + threadIdx.x; t < t1; t += RED_THREADS) {
        float4 s = *reinterpret_cast<const float4*>(
                       bias + (size_t)d * NA + t * 4);
        #pragma unroll
        for (int zz = 0; zz < CSLICES; zz++) {
            float4 p = *reinterpret_cast<const float4*>(
                           g_part + ((size_t)zz * BB + b) * NA + t * 4);
            s.x += p.x;  s.y += p.y;  s.z += p.z;  s.w += p.w;
        }
        *reinterpret_cast<float4*>(out + (size_t)b * NA + t * 4) = s;
    }
}

// ---------------------------------------------------------------------------
// Launch: metadata order = mask, features, weight, bias, instance; out = f32.
// ---------------------------------------------------------------------------
extern "C" void kernel_launch(void* const* d_in, const int* in_sizes, int n_in,
                              void* d_out, int out_size) {
    const float* mask     = (const float*)d_in[0];   // [256,1,14,14]
    const float* features = (const float*)d_in[1];   // [256,512,14,14]
    const float* weight   = (const float*)d_in[2];   // [32,512,2000]
    const float* bias     = (const float*)d_in[3];   // [32,2000]
    const int*   instance = (const int*)d_in[4];     // [256]
    float*       out      = (float*)d_out;           // [256,2000]

    // one warp per (b,c): 256*512 warps, 8 warps/block
    attend_kernel<<<(BB * CC) / 8, 256>>>(
        reinterpret_cast<const float4*>(features),
        reinterpret_cast<const float4*>(mask));

    dim3 grid(A_TILES, ND, CSLICES);
    expert_partial_kernel<<<grid, S2_THREADS>>>(weight, instance);

    dim3 rgrid(BB, RED_SPLIT);
    reduce_kernel<<<rgrid, RED_THREADS>>>(bias, instance, out);
}